// round 3
// baseline (speedup 1.0000x reference)
#include <cuda_runtime.h>
#include <math_constants.h>

#define BB 2
#define NN 512
#define HH 128
#define DD 128
#define TT 8
#define ZZ 256

#define TJ 16      // receivers (j) per block
#define CI 8       // senders (i) per chunk
#define ISPAN 64   // senders per block (8 chunks)
#define AS_LD 132  // padded lead dim (multiple of 4 -> float4-safe; mod 32 = 4 -> bank rotate)

// -------- scratch (device globals; no allocations allowed) --------
__device__ float    g_M1c[BB*NN*DD];   // z@Wm1 + bm1+bm2+bme + (graph@Wmg+bmg)
__device__ float    g_M2 [BB*NN*DD];   // z@Wm2
__device__ float    g_T1c[BB*NN*TT];   // z@Wt1 + bt1+bt2+bte + (graph@Wtg+btg)
__device__ float    g_T2 [BB*NN*TT];   // z@Wt2
__device__ float    g_o1 [BB*NN*DD];   // z@Wo1 + bo1
__device__ unsigned g_maxenc[BB*NN*DD];
__device__ float    g_gm[BB*DD];
__device__ float    g_tg[BB*TT];

// monotone float<->uint encoding for atomicMax
__device__ __forceinline__ unsigned enc_f(float f) {
    unsigned b = __float_as_uint(f);
    return (b & 0x80000000u) ? ~b : (b | 0x80000000u);
}
__device__ __forceinline__ float dec_f(unsigned u) {
    return (u & 0x80000000u) ? __uint_as_float(u ^ 0x80000000u)
                             : __uint_as_float(~u);
}

// -------- init max buffer to enc(-inf) --------
__global__ void k_init() {
    int i = blockIdx.x * blockDim.x + threadIdx.x;
    if (i < BB*NN*DD) g_maxenc[i] = 0x007FFFFFu;  // enc(-inf)
}

// -------- graph-level terms --------
__global__ void k_graph(const float* __restrict__ graph_fts,
                        const float* __restrict__ Wmg, const float* __restrict__ bmg,
                        const float* __restrict__ Wtg, const float* __restrict__ btg) {
    __shared__ float gs[HH];
    int b = blockIdx.x, t = threadIdx.x;   // 128 threads
    gs[t] = graph_fts[b*HH + t];
    __syncthreads();
    float acc = bmg[t];
    #pragma unroll 4
    for (int k = 0; k < HH; k++) acc += gs[k] * Wmg[k*DD + t];
    g_gm[b*DD + t] = acc;
    if (t < TT) {
        float a = btg[t];
        #pragma unroll 4
        for (int k = 0; k < HH; k++) a += gs[k] * Wtg[k*TT + t];
        g_tg[b*TT + t] = a;
    }
}

// -------- per-node precompute --------
__global__ void k_node(const float* __restrict__ node, const float* __restrict__ hidden,
                       const float* __restrict__ Wm1, const float* __restrict__ bm1,
                       const float* __restrict__ Wm2, const float* __restrict__ bm2,
                       const float* __restrict__ bme,
                       const float* __restrict__ Wo1, const float* __restrict__ bo1,
                       const float* __restrict__ Wt1, const float* __restrict__ bt1,
                       const float* __restrict__ Wt2, const float* __restrict__ bt2,
                       const float* __restrict__ bte) {
    __shared__ float zs[ZZ];
    int row = blockIdx.x;          // b*N + n
    int b   = row / NN;
    int t   = threadIdx.x;         // 128
    zs[t]      = node[row*HH + t];
    zs[HH + t] = hidden[row*HH + t];
    __syncthreads();
    float a1 = bm1[t] + bm2[t] + bme[t] + g_gm[b*DD + t];
    float a2 = 0.f;
    float a3 = bo1[t];
    #pragma unroll 4
    for (int k = 0; k < ZZ; k++) {
        float zk = zs[k];
        a1 += zk * Wm1[k*DD + t];
        a2 += zk * Wm2[k*DD + t];
        a3 += zk * Wo1[k*DD + t];
    }
    g_M1c[row*DD + t] = a1;
    g_M2 [row*DD + t] = a2;
    g_o1 [row*DD + t] = a3;
    if (t < 2*TT) {
        int tt = t & (TT-1), which = t >> 3;
        const float* W = which ? Wt2 : Wt1;
        float a = which ? 0.f : (bt1[tt] + bt2[tt] + bte[tt] + g_tg[b*TT + tt]);
        #pragma unroll 4
        for (int k = 0; k < ZZ; k++) a += zs[k] * W[k*TT + tt];
        if (which) g_T2[row*TT + tt] = a;
        else       g_T1c[row*TT + tt] = a;
    }
}

// -------- fused edge GEMM + triplet + masked max --------
__global__ void __launch_bounds__(256, 1)
k_main(const float* __restrict__ edge, const float* __restrict__ adj,
       const float* __restrict__ Wme, const float* __restrict__ Wte,
       float* __restrict__ tri_out) {
    extern __shared__ float smem[];
    float* Wd = smem;              // [128][128]
    float* Wt = Wd + HH*DD;        // [128][8]
    float* As = Wt + HH*TT;        // [128][AS_LD]  transposed edge tile, reused as C

    const int tid = threadIdx.x;
    const int j0  = blockIdx.x * TJ;
    const int i0  = blockIdx.y * ISPAN;
    const int b   = blockIdx.z;

    // load weights to smem (coalesced float4)
    {
        const float4* s = (const float4*)Wme; float4* d4 = (float4*)Wd;
        for (int i = tid; i < HH*DD/4; i += 256) d4[i] = s[i];
        const float4* s2 = (const float4*)Wte; float4* d2 = (float4*)Wt;
        for (int i = tid; i < HH*TT/4; i += 256) d2[i] = s2[i];
    }

    const int er = tid >> 4;          // 0..15 edge group (GEMM)
    const int cr = tid & 15;          // 0..15 col group  (GEMM)
    const int edj = tid >> 4;         // receiver within tile (epilogue)
    const int n0  = (tid & 15) * 8;   // col base (epilogue)
    const int warp = tid >> 5, lane = tid & 31;

    float m1r[8];
    {
        const float* p = &g_M1c[((size_t)b*NN + (j0 + edj))*DD + n0];
        #pragma unroll
        for (int q = 0; q < 8; q++) m1r[q] = p[q];
    }
    float rmax[8];
    #pragma unroll
    for (int q = 0; q < 8; q++) rmax[q] = -CUDART_INF_F;

    for (int ci = 0; ci < ISPAN/CI; ++ci) {
        const int i0c = i0 + ci*CI;
        __syncthreads();   // previous epilogue done reading As

        // load 128-edge x 128-k tile, transposed into As[k][e]; warp w -> sender di=w
        {
            const int di = warp;
            const float4* gp = (const float4*)(edge +
                (((size_t)b*NN + (i0c + di))*NN + j0) * (size_t)HH);
            #pragma unroll
            for (int q = 0; q < 16; q++) {
                int F4 = q*32 + lane;          // float4 index in 2048-float region
                float4 v = gp[F4];
                int F  = F4 * 4;
                int dj = F >> 7;
                int k  = F & 127;
                int e  = di*TJ + dj;
                As[(k+0)*AS_LD + e] = v.x;
                As[(k+1)*AS_LD + e] = v.y;
                As[(k+2)*AS_LD + e] = v.z;
                As[(k+3)*AS_LD + e] = v.w;
            }
        }
        __syncthreads();

        // 128x128 SGEMM tile, 8x8 per thread
        float acc[8][8];
        #pragma unroll
        for (int ii = 0; ii < 8; ii++)
            #pragma unroll
            for (int jj = 0; jj < 8; jj++) acc[ii][jj] = 0.f;

        const float* Ap = As + er*8;
        const float* Bp = Wd + cr*8;
        #pragma unroll 4
        for (int k = 0; k < HH; k++) {
            float4 a0 = *(const float4*)(Ap + k*AS_LD);
            float4 a1 = *(const float4*)(Ap + k*AS_LD + 4);
            float4 b0 = *(const float4*)(Bp + k*DD);
            float4 b1 = *(const float4*)(Bp + k*DD + 4);
            float av[8] = {a0.x,a0.y,a0.z,a0.w,a1.x,a1.y,a1.z,a1.w};
            float bv[8] = {b0.x,b0.y,b0.z,b0.w,b1.x,b1.y,b1.z,b1.w};
            #pragma unroll
            for (int ii = 0; ii < 8; ii++)
                #pragma unroll
                for (int jj = 0; jj < 8; jj++)
                    acc[ii][jj] += av[ii] * bv[jj];
        }

        // triplet columns: thread -> edge e = tid>>1, 4 cols
        float et0, et1, et2, et3;
        {
            const int e  = tid >> 1;
            const int c0 = (tid & 1) * 4;
            float s0 = 0.f, s1 = 0.f, s2 = 0.f, s3 = 0.f;
            #pragma unroll 4
            for (int k = 0; k < HH; k++) {
                float a = As[k*AS_LD + e];
                float4 w = *(const float4*)(Wt + k*TT + c0);
                s0 += a*w.x; s1 += a*w.y; s2 += a*w.z; s3 += a*w.w;
            }
            et0 = s0; et1 = s1; et2 = s2; et3 = s3;
        }
        __syncthreads();

        // stage C into smem (reuse As)
        #pragma unroll
        for (int ii = 0; ii < 8; ii++) {
            int e = er*8 + ii;
            float4 c0v = {acc[ii][0], acc[ii][1], acc[ii][2], acc[ii][3]};
            float4 c1v = {acc[ii][4], acc[ii][5], acc[ii][6], acc[ii][7]};
            *(float4*)(As + (size_t)e*AS_LD + cr*8)     = c0v;
            *(float4*)(As + (size_t)e*AS_LD + cr*8 + 4) = c1v;
        }

        // write relu'd triplet messages (pure gmem, no smem dependency)
        {
            const int e  = tid >> 1;
            const int c0 = (tid & 1) * 4;
            const int di = e >> 4, dj = e & 15;
            const int i = i0c + di, j = j0 + dj;
            const float* t1p = &g_T1c[((size_t)b*NN + j)*TT + c0];
            const float* t2p = &g_T2 [((size_t)b*NN + i)*TT + c0];
            float4 o;
            o.x = fmaxf(et0 + t1p[0] + t2p[0], 0.f);
            o.y = fmaxf(et1 + t1p[1] + t2p[1], 0.f);
            o.z = fmaxf(et2 + t1p[2] + t2p[2], 0.f);
            o.w = fmaxf(et3 + t1p[3] + t2p[3], 0.f);
            *(float4*)(tri_out + (((size_t)b*NN + i)*NN + j)*(size_t)TT + c0) = o;
        }
        __syncthreads();

        // masked max over this chunk's senders
        #pragma unroll
        for (int di = 0; di < CI; di++) {
            const int i = i0c + di;
            const float adjv = adj[((size_t)b*NN + i)*NN + (j0 + edj)];
            const int e = di*TJ + edj;
            const float* m2p = &g_M2[((size_t)b*NN + i)*DD + n0];
            float4 c0v = *(const float4*)(As + (size_t)e*AS_LD + n0);
            float4 c1v = *(const float4*)(As + (size_t)e*AS_LD + n0 + 4);
            float cv[8] = {c0v.x,c0v.y,c0v.z,c0v.w,c1v.x,c1v.y,c1v.z,c1v.w};
            #pragma unroll
            for (int q = 0; q < 8; q++) {
                float v = (cv[q] + m2p[q] + m1r[q]) * adjv;
                rmax[q] = fmaxf(rmax[q], v);
            }
        }
    }

    // merge partial max across i-split blocks
    unsigned* dst = &g_maxenc[((size_t)b*NN + (j0 + edj))*DD + n0];
    #pragma unroll
    for (int q = 0; q < 8; q++) atomicMax(dst + q, enc_f(rmax[q]));
}

// -------- output head --------
__global__ void k_final(const float* __restrict__ Wo2, const float* __restrict__ bo2,
                        float* __restrict__ ret) {
    __shared__ float ms[DD];
    int row = blockIdx.x, t = threadIdx.x;   // 128
    ms[t] = dec_f(g_maxenc[row*DD + t]);
    __syncthreads();
    float acc = g_o1[row*DD + t] + bo2[t];
    #pragma unroll 4
    for (int k = 0; k < DD; k++) acc += ms[k] * Wo2[k*DD + t];
    ret[row*DD + t] = acc;
}

extern "C" void kernel_launch(void* const* d_in, const int* in_sizes, int n_in,
                              void* d_out, int out_size) {
    (void)in_sizes; (void)n_in; (void)out_size;
    const float* node   = (const float*)d_in[0];
    const float* edge   = (const float*)d_in[1];
    const float* graph  = (const float*)d_in[2];
    const float* adj    = (const float*)d_in[3];
    const float* hidden = (const float*)d_in[4];
    const float* Wm1 = (const float*)d_in[5],  *bm1 = (const float*)d_in[6];
    const float* Wm2 = (const float*)d_in[7],  *bm2 = (const float*)d_in[8];
    const float* Wme = (const float*)d_in[9],  *bme = (const float*)d_in[10];
    const float* Wmg = (const float*)d_in[11], *bmg = (const float*)d_in[12];
    const float* Wo1 = (const float*)d_in[13], *bo1 = (const float*)d_in[14];
    const float* Wo2 = (const float*)d_in[15], *bo2 = (const float*)d_in[16];
    const float* Wt1 = (const float*)d_in[17], *bt1 = (const float*)d_in[18];
    const float* Wt2 = (const float*)d_in[19], *bt2 = (const float*)d_in[20];
    const float* Wte = (const float*)d_in[21], *bte = (const float*)d_in[22];
    const float* Wtg = (const float*)d_in[23], *btg = (const float*)d_in[24];

    float* ret = (float*)d_out;                              // [B,N,D]
    float* tri = (float*)d_out + (size_t)BB*NN*DD;           // [B,N,N,T]

    const int smem_main = (HH*DD + HH*TT + HH*AS_LD) * (int)sizeof(float); // 137216 B
    cudaFuncSetAttribute(k_main, cudaFuncAttributeMaxDynamicSharedMemorySize, smem_main);

    k_init<<<(BB*NN*DD + 255)/256, 256>>>();
    k_graph<<<BB, 128>>>(graph, Wmg, bmg, Wtg, btg);
    k_node<<<BB*NN, 128>>>(node, hidden, Wm1, bm1, Wm2, bm2, bme,
                           Wo1, bo1, Wt1, bt1, Wt2, bt2, bte);
    k_main<<<dim3(NN/TJ, NN/ISPAN, BB), 256, smem_main>>>(edge, adj, Wme, Wte, tri);
    k_final<<<BB*NN, 128>>>(Wo2, bo2, ret);
}

// round 5
// speedup vs baseline: 1.4152x; 1.4152x over previous
#include <cuda_runtime.h>
#include <cuda_bf16.h>
#include <math_constants.h>
#include <cstdint>

#define BB 2
#define NN 512
#define HH 128
#define DD 128
#define TT 8
#define ZZ 256

#define TJ 16          // receivers per tile
#define CI 8           // senders per tile (chunk)
#define ISPAN 64       // senders per block
#define IGRP (NN/ISPAN)   // 8 sender groups
#define NCHUNK (ISPAN/CI) // 8 chunks per block

#define ALD 136        // k lead dim (bf16 elems) for A and B: conflict-free frags
// ---- smem offsets (bytes) ----
#define OFF_BH  0
#define OFF_BL  34816
#define OFF_AH  69632
#define OFF_AL  104448
#define OFF_BTH 139264
#define OFF_BTL 141440
#define SMEM_MAIN 143616
// C overlay: float[128][136] at OFF_AH (69632 bytes = AH+AL exactly)

// ---------------- scratch ----------------
__device__ float g_M1c[BB*NN*DD];
__device__ float g_M2 [BB*NN*DD];
__device__ float g_T1c[BB*NN*TT];
__device__ float g_T2 [BB*NN*TT];
__device__ float g_o1 [BB*NN*DD];
__device__ float g_gm [BB*DD];
__device__ float g_tg [BB*TT];
__device__ float g_part[IGRP*BB*NN*DD];   // per-group masked-max partials (4 MB)

// fp32 -> bf16 hi(trunc)/lo(rn) split for two floats, packed bf16x2
__device__ __forceinline__ void cvt_hilo(float x, float y, unsigned &hi, unsigned &lo) {
    unsigned bx = __float_as_uint(x) & 0xFFFF0000u;
    unsigned by = __float_as_uint(y) & 0xFFFF0000u;
    hi = __byte_perm(bx, by, 0x7632);          // low=hi(x), high=hi(y)
    float lx = x - __uint_as_float(bx);
    float ly = y - __uint_as_float(by);
    asm("cvt.rn.bf16x2.f32 %0, %1, %2;" : "=r"(lo) : "f"(ly), "f"(lx));
}

__device__ __forceinline__ void mma16816(float* c, const uint32_t* a, uint32_t b0, uint32_t b1) {
    asm volatile(
        "mma.sync.aligned.m16n8k16.row.col.f32.bf16.bf16.f32 "
        "{%0,%1,%2,%3}, {%4,%5,%6,%7}, {%8,%9}, {%0,%1,%2,%3};"
        : "+f"(c[0]), "+f"(c[1]), "+f"(c[2]), "+f"(c[3])
        : "r"(a[0]), "r"(a[1]), "r"(a[2]), "r"(a[3]), "r"(b0), "r"(b1));
}

// -------- graph-level terms --------
__global__ void k_graph(const float* __restrict__ graph_fts,
                        const float* __restrict__ Wmg, const float* __restrict__ bmg,
                        const float* __restrict__ Wtg, const float* __restrict__ btg) {
    __shared__ float gs[HH];
    int b = blockIdx.x, t = threadIdx.x;
    gs[t] = graph_fts[b*HH + t];
    __syncthreads();
    float acc = bmg[t];
    #pragma unroll 4
    for (int k = 0; k < HH; k++) acc += gs[k] * Wmg[k*DD + t];
    g_gm[b*DD + t] = acc;
    if (t < TT) {
        float a = btg[t];
        #pragma unroll 4
        for (int k = 0; k < HH; k++) a += gs[k] * Wtg[k*TT + t];
        g_tg[b*TT + t] = a;
    }
}

// -------- per-node precompute: 8 rows per block --------
__global__ void k_node(const float* __restrict__ node, const float* __restrict__ hidden,
                       const float* __restrict__ Wm1, const float* __restrict__ bm1,
                       const float* __restrict__ Wm2, const float* __restrict__ bm2,
                       const float* __restrict__ bme,
                       const float* __restrict__ Wo1, const float* __restrict__ bo1,
                       const float* __restrict__ Wt1, const float* __restrict__ bt1,
                       const float* __restrict__ Wt2, const float* __restrict__ bt2,
                       const float* __restrict__ bte) {
    __shared__ float zs[8][ZZ];
    const int row0 = blockIdx.x * 8;
    const int b    = row0 / NN;
    const int t    = threadIdx.x;   // 128
    #pragma unroll
    for (int r = 0; r < 8; r++) {
        zs[r][t]      = node[(row0 + r)*HH + t];
        zs[r][HH + t] = hidden[(row0 + r)*HH + t];
    }
    __syncthreads();
    float a1[8], a2[8], a3[8];
    const float bia = bm1[t] + bm2[t] + bme[t] + g_gm[b*DD + t];
    const float bio = bo1[t];
    #pragma unroll
    for (int r = 0; r < 8; r++) { a1[r] = bia; a2[r] = 0.f; a3[r] = bio; }
    for (int k = 0; k < ZZ; k++) {
        float w1 = Wm1[k*DD + t], w2 = Wm2[k*DD + t], w3 = Wo1[k*DD + t];
        #pragma unroll
        for (int r = 0; r < 8; r++) {
            float zk = zs[r][k];
            a1[r] += zk*w1; a2[r] += zk*w2; a3[r] += zk*w3;
        }
    }
    #pragma unroll
    for (int r = 0; r < 8; r++) {
        g_M1c[(row0 + r)*DD + t] = a1[r];
        g_M2 [(row0 + r)*DD + t] = a2[r];
        g_o1 [(row0 + r)*DD + t] = a3[r];
    }
    {   // triplet heads: (row = t>>4, which = (t>>3)&1, tt = t&7)
        int r = t >> 4, which = (t >> 3) & 1, tt = t & 7;
        const float* W = which ? Wt2 : Wt1;
        float a = which ? 0.f : (bt1[tt] + bt2[tt] + bte[tt] + g_tg[b*TT + tt]);
        #pragma unroll 4
        for (int k = 0; k < ZZ; k++) a += zs[r][k] * W[k*TT + tt];
        if (which) g_T2 [(row0 + r)*TT + tt] = a;
        else       g_T1c[(row0 + r)*TT + tt] = a;
    }
}

// -------- fused edge GEMM (mma.sync bf16 hi/lo) + triplet + masked max --------
__global__ void __launch_bounds__(256, 1)
k_main(const float* __restrict__ edge, const float* __restrict__ adj,
       const float* __restrict__ Wme, const float* __restrict__ Wte,
       float* __restrict__ tri_out) {
    extern __shared__ char sm[];
    const int tid  = threadIdx.x;
    const int wid  = tid >> 5, lane = tid & 31;
    const int qr   = lane >> 2, qc = lane & 3;
    const int wm   = wid >> 2, wn = wid & 3;     // 2m x 4n warp grid
    const int jb   = blockIdx.x, ig = blockIdx.y, b = blockIdx.z;
    const int j0   = jb * TJ;
    const int i0   = ig * ISPAN;

    // ---- convert B = Wme (128k x 128n) to [n][k] bf16 hi/lo
    for (int idx = tid; idx < HH*DD; idx += 256) {
        int k = idx >> 7, n = idx & 127;
        float w = Wme[idx];
        unsigned bw = __float_as_uint(w) & 0xFFFF0000u;
        *(unsigned short*)(sm + OFF_BH + (n*ALD + k)*2) = (unsigned short)(bw >> 16);
        *(__nv_bfloat16*)(sm + OFF_BL + (n*ALD + k)*2) = __float2bfloat16(w - __uint_as_float(bw));
    }
    // ---- Wte (128k x 8t) to [t][k] bf16 hi/lo
    for (int idx = tid; idx < HH*TT; idx += 256) {
        int k = idx >> 3, n = idx & 7;
        float w = Wte[idx];
        unsigned bw = __float_as_uint(w) & 0xFFFF0000u;
        *(unsigned short*)(sm + OFF_BTH + (n*ALD + k)*2) = (unsigned short)(bw >> 16);
        *(__nv_bfloat16*)(sm + OFF_BTL + (n*ALD + k)*2) = __float2bfloat16(w - __uint_as_float(bw));
    }

    // epilogue thread roles
    const int edj = tid >> 4;          // receiver within tile
    const int n0e = (tid & 15) * 8;    // msg col base
    const int te  = tid >> 1;          // edge for tri
    const int tc  = (tid & 1) * 4;     // tri col base
    float rmax[8];
    #pragma unroll
    for (int q = 0; q < 8; q++) rmax[q] = -CUDART_INF_F;
    bool sawz = false;
    float* Cf = (float*)(sm + OFF_AH);  // C overlay [128][ALD] f32

    const uint32_t aoffs[3] = {OFF_AH, OFF_AH, OFF_AL};
    const uint32_t boffs[3] = {OFF_BH, OFF_BL, OFF_BH};
    const uint32_t btoffs[3] = {OFF_BTH, OFF_BTL, OFF_BTH};

    for (int ci = 0; ci < NCHUNK; ci++) {
        const int i0c = i0 + ci*CI;
        __syncthreads();   // prev epilogue done reading C (overlay of A)

        // ---- convert edge tile (CI senders x TJ receivers = 128 edges x 128 k)
        {
            const size_t base = ((size_t)b*NN)*NN*HH;
            #pragma unroll
            for (int q = 0; q < 16; q++) {
                int F4 = q*256 + tid;               // 4096 float4s
                int e  = F4 >> 5;                   // edge 0..127
                int k  = (F4 & 31) << 2;            // k multiple of 4
                int di = e >> 4, dj = e & 15;
                const float4 v = *(const float4*)(edge + base
                    + ((size_t)(i0c + di)*NN + (j0 + dj))*(size_t)HH + k);
                unsigned h01, l01, h23, l23;
                cvt_hilo(v.x, v.y, h01, l01);
                cvt_hilo(v.z, v.w, h23, l23);
                uint2 hv = make_uint2(h01, h23), lv = make_uint2(l01, l23);
                *(uint2*)(sm + OFF_AH + (e*ALD + k)*2) = hv;
                *(uint2*)(sm + OFF_AL + (e*ALD + k)*2) = lv;
            }
        }
        __syncthreads();

        // ---- MMA: 3 products, 8 ksteps, 4m x 4n per warp + 1 tri tile
        float c[4][4][4];
        float ct[4];
        #pragma unroll
        for (int mt = 0; mt < 4; mt++)
            #pragma unroll
            for (int nt = 0; nt < 4; nt++)
                #pragma unroll
                for (int q = 0; q < 4; q++) c[mt][nt][q] = 0.f;
        #pragma unroll
        for (int q = 0; q < 4; q++) ct[q] = 0.f;

        #pragma unroll
        for (int p = 0; p < 3; p++) {
            const char* Ap  = sm + aoffs[p];
            const char* Bp  = sm + boffs[p];
            const char* Btp = sm + btoffs[p];
            #pragma unroll 2
            for (int ks = 0; ks < 8; ks++) {
                uint32_t a[4][4];
                #pragma unroll
                for (int mt = 0; mt < 4; mt++) {
                    const char* ab = Ap + ((wm*64 + mt*16 + qr)*ALD + ks*16 + 2*qc)*2;
                    a[mt][0] = *(const uint32_t*)ab;
                    a[mt][1] = *(const uint32_t*)(ab + 8*ALD*2);
                    a[mt][2] = *(const uint32_t*)(ab + 16);
                    a[mt][3] = *(const uint32_t*)(ab + 8*ALD*2 + 16);
                }
                #pragma unroll
                for (int nt = 0; nt < 4; nt++) {
                    const char* bb = Bp + ((wn*32 + nt*8 + qr)*ALD + ks*16 + 2*qc)*2;
                    uint32_t b0 = *(const uint32_t*)bb;
                    uint32_t b1 = *(const uint32_t*)(bb + 16);
                    #pragma unroll
                    for (int mt = 0; mt < 4; mt++) mma16816(c[mt][nt], a[mt], b0, b1);
                }
                {   // tri tile: warp's m-tile index = wn, reuse a[wn]
                    const char* bb = Btp + ((qr)*ALD + ks*16 + 2*qc)*2;
                    uint32_t b0 = *(const uint32_t*)bb;
                    uint32_t b1 = *(const uint32_t*)(bb + 16);
                    mma16816(ct, a[wn], b0, b1);
                }
            }
        }
        __syncthreads();   // all A reads done; safe to overlay C

        // ---- stage C (msg cols + tri cols)
        #pragma unroll
        for (int mt = 0; mt < 4; mt++) {
            int e = wm*64 + mt*16 + qr;
            #pragma unroll
            for (int nt = 0; nt < 4; nt++) {
                int n = wn*32 + nt*8 + 2*qc;
                *(float2*)(Cf + e*ALD + n)       = make_float2(c[mt][nt][0], c[mt][nt][1]);
                *(float2*)(Cf + (e+8)*ALD + n)   = make_float2(c[mt][nt][2], c[mt][nt][3]);
            }
        }
        {
            int e = wm*64 + wn*16 + qr;
            int n = 128 + 2*qc;
            *(float2*)(Cf + e*ALD + n)     = make_float2(ct[0], ct[1]);
            *(float2*)(Cf + (e+8)*ALD + n) = make_float2(ct[2], ct[3]);
        }
        __syncthreads();

        // ---- tri write (relu(C_tri + t1 + t2))
        {
            const int di = te >> 4, dj = te & 15;
            const int i = i0c + di, j = j0 + dj;
            float4 cv = *(const float4*)(Cf + te*ALD + 128 + tc);
            const float* t1p = &g_T1c[((size_t)b*NN + j)*TT + tc];
            const float* t2p = &g_T2 [((size_t)b*NN + i)*TT + tc];
            float4 o;
            o.x = fmaxf(cv.x + t1p[0] + t2p[0], 0.f);
            o.y = fmaxf(cv.y + t1p[1] + t2p[1], 0.f);
            o.z = fmaxf(cv.z + t1p[2] + t2p[2], 0.f);
            o.w = fmaxf(cv.w + t1p[3] + t2p[3], 0.f);
            *(float4*)(tri_out + (((size_t)b*NN + i)*NN + j)*(size_t)TT + tc) = o;
        }
        // ---- masked max over this chunk's senders
        #pragma unroll
        for (int di = 0; di < CI; di++) {
            const int i = i0c + di;
            const float adjv = adj[((size_t)b*NN + i)*NN + (j0 + edj)];
            if (adjv != 0.0f) {
                const int e = di*TJ + edj;
                const float* m2p = &g_M2[((size_t)b*NN + i)*DD + n0e];
                float4 c0v = *(const float4*)(Cf + e*ALD + n0e);
                float4 c1v = *(const float4*)(Cf + e*ALD + n0e + 4);
                rmax[0] = fmaxf(rmax[0], c0v.x + m2p[0]);
                rmax[1] = fmaxf(rmax[1], c0v.y + m2p[1]);
                rmax[2] = fmaxf(rmax[2], c0v.z + m2p[2]);
                rmax[3] = fmaxf(rmax[3], c0v.w + m2p[3]);
                rmax[4] = fmaxf(rmax[4], c1v.x + m2p[4]);
                rmax[5] = fmaxf(rmax[5], c1v.y + m2p[5]);
                rmax[6] = fmaxf(rmax[6], c1v.z + m2p[6]);
                rmax[7] = fmaxf(rmax[7], c1v.w + m2p[7]);
            } else {
                sawz = true;
            }
        }
    }

    // ---- fold m1 + write group partial
    {
        const float* m1p = &g_M1c[((size_t)b*NN + j0 + edj)*DD + n0e];
        float* op = &g_part[(((size_t)ig*BB + b)*NN + (j0 + edj))*DD + n0e];
        const float z = sawz ? 0.0f : -CUDART_INF_F;
        #pragma unroll
        for (int q = 0; q < 8; q += 4) {
            float4 m = *(const float4*)(m1p + q);
            float4 o;
            o.x = fmaxf(rmax[q+0] + m.x, z);
            o.y = fmaxf(rmax[q+1] + m.y, z);
            o.z = fmaxf(rmax[q+2] + m.z, z);
            o.w = fmaxf(rmax[q+3] + m.w, z);
            *(float4*)(op + q) = o;
        }
    }
}

// -------- output head: reduce partials + Wo2 GEMM, 8 rows per block --------
__global__ void k_final(const float* __restrict__ Wo2, const float* __restrict__ bo2,
                        float* __restrict__ ret) {
    __shared__ float ms[8][DD];
    const int row0 = blockIdx.x * 8;
    const int t = threadIdx.x;      // 128
    #pragma unroll
    for (int r = 0; r < 8; r++) {
        float v = -CUDART_INF_F;
        #pragma unroll
        for (int g = 0; g < IGRP; g++)
            v = fmaxf(v, g_part[(size_t)g*BB*NN*DD + (size_t)(row0 + r)*DD + t]);
        ms[r][t] = v;
    }
    __syncthreads();
    float acc[8];
    const float bia = bo2[t];
    #pragma unroll
    for (int r = 0; r < 8; r++) acc[r] = g_o1[(row0 + r)*DD + t] + bia;
    for (int k = 0; k < DD; k++) {
        float w = Wo2[k*DD + t];
        #pragma unroll
        for (int r = 0; r < 8; r++) acc[r] += ms[r][k] * w;
    }
    #pragma unroll
    for (int r = 0; r < 8; r++) ret[(row0 + r)*DD + t] = acc[r];
}

extern "C" void kernel_launch(void* const* d_in, const int* in_sizes, int n_in,
                              void* d_out, int out_size) {
    (void)in_sizes; (void)n_in; (void)out_size;
    const float* node   = (const float*)d_in[0];
    const float* edge   = (const float*)d_in[1];
    const float* graph  = (const float*)d_in[2];
    const float* adj    = (const float*)d_in[3];
    const float* hidden = (const float*)d_in[4];
    const float* Wm1 = (const float*)d_in[5],  *bm1 = (const float*)d_in[6];
    const float* Wm2 = (const float*)d_in[7],  *bm2 = (const float*)d_in[8];
    const float* Wme = (const float*)d_in[9],  *bme = (const float*)d_in[10];
    const float* Wmg = (const float*)d_in[11], *bmg = (const float*)d_in[12];
    const float* Wo1 = (const float*)d_in[13], *bo1 = (const float*)d_in[14];
    const float* Wo2 = (const float*)d_in[15], *bo2 = (const float*)d_in[16];
    const float* Wt1 = (const float*)d_in[17], *bt1 = (const float*)d_in[18];
    const float* Wt2 = (const float*)d_in[19], *bt2 = (const float*)d_in[20];
    const float* Wte = (const float*)d_in[21], *bte = (const float*)d_in[22];
    const float* Wtg = (const float*)d_in[23], *btg = (const float*)d_in[24];

    float* ret = (float*)d_out;
    float* tri = (float*)d_out + (size_t)BB*NN*DD;

    cudaFuncSetAttribute(k_main, cudaFuncAttributeMaxDynamicSharedMemorySize, SMEM_MAIN);

    k_graph<<<BB, 128>>>(graph, Wmg, bmg, Wtg, btg);
    k_node<<<BB*NN/8, 128>>>(node, hidden, Wm1, bm1, Wm2, bm2, bme,
                             Wo1, bo1, Wt1, bt1, Wt2, bt2, bte);
    k_main<<<dim3(NN/TJ, IGRP, BB), 256, SMEM_MAIN>>>(edge, adj, Wme, Wte, tri);
    k_final<<<BB*NN/8, 128>>>(Wo2, bo2, ret);
}

// round 6
// speedup vs baseline: 1.7192x; 1.2148x over previous
#include <cuda_runtime.h>
#include <cuda_bf16.h>
#include <math_constants.h>
#include <cstdint>

#define BB 2
#define NN 512
#define HH 128
#define DD 128
#define TT 8
#define ZZ 256

#define NTH 512
#define TJ 16             // receivers per tile
#define CI 8              // senders per chunk
#define ISPAN 64          // senders per block
#define IGRP (NN/ISPAN)   // 8 sender groups
#define NCHUNK (ISPAN/CI) // 8 chunks

#define ALD 136           // lead dim (bf16 elems / f32 elems for C)
// ---- smem offsets (bytes) ----
#define OFF_BH   0
#define OFF_BL   34816
#define OFF_AH   69632
#define OFF_AL   104448
#define OFF_BTH  139264
#define OFF_BTL  141440
#define OFF_STG  143616     // fp32 staging 64KB
#define SMEM_MAIN 209152
// C overlay: float[128][136] at OFF_AH (69632 B = AH+AL)

// ---------------- scratch ----------------
__device__ float g_M1c[BB*NN*DD];
__device__ float g_M2 [BB*NN*DD];
__device__ float g_T1c[BB*NN*TT];
__device__ float g_T2 [BB*NN*TT];
__device__ float g_o1 [BB*NN*DD];
__device__ float g_gm [BB*DD];
__device__ float g_tg [BB*TT];
__device__ float g_part[IGRP*BB*NN*DD];

__device__ __forceinline__ uint32_t smem_u32(const void* p) {
    uint32_t a;
    asm("{ .reg .u64 t; cvta.to.shared.u64 t, %1; cvt.u32.u64 %0, t; }" : "=r"(a) : "l"(p));
    return a;
}
__device__ __forceinline__ void cvt_hilo(float x, float y, unsigned &hi, unsigned &lo) {
    unsigned bx = __float_as_uint(x) & 0xFFFF0000u;
    unsigned by = __float_as_uint(y) & 0xFFFF0000u;
    hi = __byte_perm(bx, by, 0x7632);
    float lx = x - __uint_as_float(bx);
    float ly = y - __uint_as_float(by);
    asm("cvt.rn.bf16x2.f32 %0, %1, %2;" : "=r"(lo) : "f"(ly), "f"(lx));
}
__device__ __forceinline__ void mma16816(float* c, const uint32_t* a, uint32_t b0, uint32_t b1) {
    asm volatile(
        "mma.sync.aligned.m16n8k16.row.col.f32.bf16.bf16.f32 "
        "{%0,%1,%2,%3}, {%4,%5,%6,%7}, {%8,%9}, {%0,%1,%2,%3};"
        : "+f"(c[0]), "+f"(c[1]), "+f"(c[2]), "+f"(c[3])
        : "r"(a[0]), "r"(a[1]), "r"(a[2]), "r"(a[3]), "r"(b0), "r"(b1));
}
#define LDMX4(r0,r1,r2,r3,addr) \
    asm volatile("ldmatrix.sync.aligned.m8n8.x4.shared.b16 {%0,%1,%2,%3}, [%4];" \
        : "=r"(r0),"=r"(r1),"=r"(r2),"=r"(r3) : "r"(addr))
#define LDMX2(r0,r1,addr) \
    asm volatile("ldmatrix.sync.aligned.m8n8.x2.shared.b16 {%0,%1}, [%2];" \
        : "=r"(r0),"=r"(r1) : "r"(addr))
#define CP_ASYNC16(dst, src) \
    asm volatile("cp.async.cg.shared.global [%0], [%1], 16;" :: "r"(dst), "l"(src) : "memory")
#define CP_COMMIT() asm volatile("cp.async.commit_group;" ::: "memory")
#define CP_WAIT0()  asm volatile("cp.async.wait_group 0;" ::: "memory")

// -------- graph-level terms --------
__global__ void k_graph(const float* __restrict__ graph_fts,
                        const float* __restrict__ Wmg, const float* __restrict__ bmg,
                        const float* __restrict__ Wtg, const float* __restrict__ btg) {
    __shared__ float gs[HH];
    int b = blockIdx.x, t = threadIdx.x;
    gs[t] = graph_fts[b*HH + t];
    __syncthreads();
    float acc = bmg[t];
    #pragma unroll 4
    for (int k = 0; k < HH; k++) acc += gs[k] * Wmg[k*DD + t];
    g_gm[b*DD + t] = acc;
    if (t < TT) {
        float a = btg[t];
        #pragma unroll 4
        for (int k = 0; k < HH; k++) a += gs[k] * Wtg[k*TT + t];
        g_tg[b*TT + t] = a;
    }
}

// -------- per-node precompute: 8 rows per block --------
__global__ void k_node(const float* __restrict__ node, const float* __restrict__ hidden,
                       const float* __restrict__ Wm1, const float* __restrict__ bm1,
                       const float* __restrict__ Wm2, const float* __restrict__ bm2,
                       const float* __restrict__ bme,
                       const float* __restrict__ Wo1, const float* __restrict__ bo1,
                       const float* __restrict__ Wt1, const float* __restrict__ bt1,
                       const float* __restrict__ Wt2, const float* __restrict__ bt2,
                       const float* __restrict__ bte) {
    __shared__ float zs[8][ZZ];
    const int row0 = blockIdx.x * 8;
    const int b    = row0 / NN;
    const int t    = threadIdx.x;   // 128
    #pragma unroll
    for (int r = 0; r < 8; r++) {
        zs[r][t]      = node[(row0 + r)*HH + t];
        zs[r][HH + t] = hidden[(row0 + r)*HH + t];
    }
    __syncthreads();
    float a1[8], a2[8], a3[8];
    const float bia = bm1[t] + bm2[t] + bme[t] + g_gm[b*DD + t];
    const float bio = bo1[t];
    #pragma unroll
    for (int r = 0; r < 8; r++) { a1[r] = bia; a2[r] = 0.f; a3[r] = bio; }
    for (int k = 0; k < ZZ; k++) {
        float w1 = Wm1[k*DD + t], w2 = Wm2[k*DD + t], w3 = Wo1[k*DD + t];
        #pragma unroll
        for (int r = 0; r < 8; r++) {
            float zk = zs[r][k];
            a1[r] += zk*w1; a2[r] += zk*w2; a3[r] += zk*w3;
        }
    }
    #pragma unroll
    for (int r = 0; r < 8; r++) {
        g_M1c[(row0 + r)*DD + t] = a1[r];
        g_M2 [(row0 + r)*DD + t] = a2[r];
        g_o1 [(row0 + r)*DD + t] = a3[r];
    }
    {
        int r = t >> 4, which = (t >> 3) & 1, tt = t & 7;
        const float* W = which ? Wt2 : Wt1;
        float a = which ? 0.f : (bt1[tt] + bt2[tt] + bte[tt] + g_tg[b*TT + tt]);
        #pragma unroll 4
        for (int k = 0; k < ZZ; k++) a += zs[r][k] * W[k*TT + tt];
        if (which) g_T2 [(row0 + r)*TT + tt] = a;
        else       g_T1c[(row0 + r)*TT + tt] = a;
    }
}

// -------- fused edge GEMM (mma.sync bf16 hi/lo, pipelined) --------
__global__ void __launch_bounds__(NTH, 1)
k_main(const float* __restrict__ edge, const float* __restrict__ adj,
       const float* __restrict__ Wme, const float* __restrict__ Wte,
       float* __restrict__ tri_out, int ig_base) {
    extern __shared__ char sm[];
    const uint32_t smb = smem_u32(sm);
    const int tid  = threadIdx.x;
    const int lane = tid & 31, wid = tid >> 5;
    const int qr   = lane >> 2, qc = lane & 3;
    const int wm   = wid >> 2, wn = wid & 3;     // 4m x 4n warp grid
    const int jb   = blockIdx.x, ig = ig_base + blockIdx.y, b = blockIdx.z;
    const int j0   = jb * TJ;
    const int i0   = ig * ISPAN;

    // ---- prefetch chunk 0
    {
        const size_t base = ((size_t)b*NN)*NN*HH;
        #pragma unroll
        for (int q = 0; q < 8; q++) {
            int F4 = q*NTH + tid;
            int e  = F4 >> 5, k = (F4 & 31) << 2;
            int di = e >> 4, dj = e & 15;
            const float* src = edge + base + ((size_t)(i0 + di)*NN + (j0 + dj))*(size_t)HH + k;
            CP_ASYNC16(smb + OFF_STG + F4*16, src);
        }
        CP_COMMIT();
    }

    // ---- convert B = Wme -> [n][k] bf16 hi/lo
    for (int idx = tid; idx < HH*DD; idx += NTH) {
        int k = idx >> 7, n = idx & 127;
        float w = Wme[idx];
        unsigned bw = __float_as_uint(w) & 0xFFFF0000u;
        *(unsigned short*)(sm + OFF_BH + (n*ALD + k)*2) = (unsigned short)(bw >> 16);
        *(__nv_bfloat16*)(sm + OFF_BL + (n*ALD + k)*2) = __float2bfloat16(w - __uint_as_float(bw));
    }
    for (int idx = tid; idx < HH*TT; idx += NTH) {
        int k = idx >> 3, n = idx & 7;
        float w = Wte[idx];
        unsigned bw = __float_as_uint(w) & 0xFFFF0000u;
        *(unsigned short*)(sm + OFF_BTH + (n*ALD + k)*2) = (unsigned short)(bw >> 16);
        *(__nv_bfloat16*)(sm + OFF_BTL + (n*ALD + k)*2) = __float2bfloat16(w - __uint_as_float(bw));
    }

    // fragment base offsets (ldmatrix lane addressing)
    const uint32_t aoff  = (uint32_t)(((wm*32 + (lane & 15))*ALD + ((lane >> 4) << 3)) * 2);
    const uint32_t boff  = (uint32_t)(((wn*32 + ((lane >> 4) << 3) + (lane & 7))*ALD + (((lane >> 3) & 1) << 3)) * 2);
    const uint32_t btoff = (uint32_t)(((lane & 7)*ALD + (((lane >> 3) & 1) << 3)) * 2);
    const uint32_t aHb = smb + OFF_AH + aoff,  aLb = smb + OFF_AL + aoff;
    const uint32_t bHb = smb + OFF_BH + boff,  bLb = smb + OFF_BL + boff;
    const uint32_t tHb = smb + OFF_BTH + btoff, tLb = smb + OFF_BTL + btoff;

    // epilogue roles
    const int edj = tid >> 5;           // receiver 0..15
    const int n0e = (lane) * 4;         // col base 0..124
    const int te  = tid >> 2;           // edge 0..127 (tri)
    const int tc  = (tid & 3) * 2;      // tri col base
    float rmax[4] = {-CUDART_INF_F, -CUDART_INF_F, -CUDART_INF_F, -CUDART_INF_F};
    bool sawz = false;
    float* Cf = (float*)(sm + OFF_AH);

    for (int ci = 0; ci < NCHUNK; ci++) {
        const int i0c = i0 + ci*CI;
        CP_WAIT0();
        __syncthreads();   // staging ready; prev epilogue smem reads done

        // ---- convert staging fp32 -> A hi/lo
        {
            const float4* stg = (const float4*)(sm + OFF_STG);
            #pragma unroll
            for (int q = 0; q < 8; q++) {
                int F4 = q*NTH + tid;
                float4 v = stg[F4];
                int e = F4 >> 5, k = (F4 & 31) << 2;
                unsigned h01, l01, h23, l23;
                cvt_hilo(v.x, v.y, h01, l01);
                cvt_hilo(v.z, v.w, h23, l23);
                *(uint2*)(sm + OFF_AH + (e*ALD + k)*2) = make_uint2(h01, h23);
                *(uint2*)(sm + OFF_AL + (e*ALD + k)*2) = make_uint2(l01, l23);
            }
        }
        __syncthreads();

        // ---- prefetch next chunk (overlaps MMA)
        if (ci + 1 < NCHUNK) {
            const size_t base = ((size_t)b*NN)*NN*HH;
            const int i0n = i0c + CI;
            #pragma unroll
            for (int q = 0; q < 8; q++) {
                int F4 = q*NTH + tid;
                int e  = F4 >> 5, k = (F4 & 31) << 2;
                int di = e >> 4, dj = e & 15;
                const float* src = edge + base + ((size_t)(i0n + di)*NN + (j0 + dj))*(size_t)HH + k;
                CP_ASYNC16(smb + OFF_STG + F4*16, src);
            }
            CP_COMMIT();
        }

        // ---- MMA: fused 3 products, ldmatrix frags
        float c[2][4][4];
        float ct[4] = {0.f, 0.f, 0.f, 0.f};
        #pragma unroll
        for (int mt = 0; mt < 2; mt++)
            #pragma unroll
            for (int nt = 0; nt < 4; nt++)
                #pragma unroll
                for (int q = 0; q < 4; q++) c[mt][nt][q] = 0.f;

        #pragma unroll
        for (int ks = 0; ks < 8; ks++) {
            const uint32_t kb = ks * 32;
            uint32_t aH[2][4], aL[2][4], bH[2][4], bL[2][4];
            LDMX4(aH[0][0], aH[0][1], aH[0][2], aH[0][3], aHb + kb);
            LDMX4(aH[1][0], aH[1][1], aH[1][2], aH[1][3], aHb + 16*ALD*2 + kb);
            LDMX4(aL[0][0], aL[0][1], aL[0][2], aL[0][3], aLb + kb);
            LDMX4(aL[1][0], aL[1][1], aL[1][2], aL[1][3], aLb + 16*ALD*2 + kb);
            LDMX4(bH[0][0], bH[0][1], bH[0][2], bH[0][3], bHb + kb);
            LDMX4(bH[1][0], bH[1][1], bH[1][2], bH[1][3], bHb + 16*ALD*2 + kb);
            LDMX4(bL[0][0], bL[0][1], bL[0][2], bL[0][3], bLb + kb);
            LDMX4(bL[1][0], bL[1][1], bL[1][2], bL[1][3], bLb + 16*ALD*2 + kb);
            #pragma unroll
            for (int nt = 0; nt < 4; nt++) {
                uint32_t b0h = bH[nt>>1][(nt&1)*2], b1h = bH[nt>>1][(nt&1)*2+1];
                uint32_t b0l = bL[nt>>1][(nt&1)*2], b1l = bL[nt>>1][(nt&1)*2+1];
                #pragma unroll
                for (int mt = 0; mt < 2; mt++) {
                    mma16816(c[mt][nt], aH[mt], b0h, b1h);
                    mma16816(c[mt][nt], aH[mt], b0l, b1l);
                    mma16816(c[mt][nt], aL[mt], b0h, b1h);
                }
            }
            if (wn < 2) {   // tri tile: m-tile = wm*2 + wn
                uint32_t t0h, t1h, t0l, t1l;
                LDMX2(t0h, t1h, tHb + kb);
                LDMX2(t0l, t1l, tLb + kb);
                const uint32_t* ah = wn ? aH[1] : aH[0];
                const uint32_t* al = wn ? aL[1] : aL[0];
                mma16816(ct, ah, t0h, t1h);
                mma16816(ct, ah, t0l, t1l);
                mma16816(ct, al, t0h, t1h);
            }
        }
        __syncthreads();   // A reads done; C overlay safe

        // ---- stage C
        #pragma unroll
        for (int mt = 0; mt < 2; mt++) {
            int e = wm*32 + mt*16 + qr;
            #pragma unroll
            for (int nt = 0; nt < 4; nt++) {
                int n = wn*32 + nt*8 + 2*qc;
                *(float2*)(Cf + e*ALD + n)     = make_float2(c[mt][nt][0], c[mt][nt][1]);
                *(float2*)(Cf + (e+8)*ALD + n) = make_float2(c[mt][nt][2], c[mt][nt][3]);
            }
        }
        if (wn < 2) {
            int e = wm*32 + wn*16 + qr;
            int n = 128 + 2*qc;
            *(float2*)(Cf + e*ALD + n)     = make_float2(ct[0], ct[1]);
            *(float2*)(Cf + (e+8)*ALD + n) = make_float2(ct[2], ct[3]);
        }
        __syncthreads();

        // ---- tri write
        {
            const int di = te >> 4, dj = te & 15;
            const int i = i0c + di, j = j0 + dj;
            float2 cv = *(const float2*)(Cf + te*ALD + 128 + tc);
            float2 t1 = *(const float2*)(&g_T1c[((size_t)b*NN + j)*TT + tc]);
            float2 t2 = *(const float2*)(&g_T2 [((size_t)b*NN + i)*TT + tc]);
            float2 o;
            o.x = fmaxf(cv.x + t1.x + t2.x, 0.f);
            o.y = fmaxf(cv.y + t1.y + t2.y, 0.f);
            *(float2*)(tri_out + (((size_t)b*NN + i)*NN + j)*(size_t)TT + tc) = o;
        }
        // ---- masked max over this chunk's senders
        #pragma unroll
        for (int di = 0; di < CI; di++) {
            const int i = i0c + di;
            const float adjv = adj[((size_t)b*NN + i)*NN + (j0 + edj)];
            if (adjv != 0.0f) {
                float4 m2 = *(const float4*)(&g_M2[((size_t)b*NN + i)*DD + n0e]);
                float4 cv = *(const float4*)(Cf + (di*TJ + edj)*ALD + n0e);
                rmax[0] = fmaxf(rmax[0], cv.x + m2.x);
                rmax[1] = fmaxf(rmax[1], cv.y + m2.y);
                rmax[2] = fmaxf(rmax[2], cv.z + m2.z);
                rmax[3] = fmaxf(rmax[3], cv.w + m2.w);
            } else {
                sawz = true;
            }
        }
    }

    // ---- fold m1 + write group partial
    {
        float4 m1 = *(const float4*)(&g_M1c[((size_t)b*NN + j0 + edj)*DD + n0e]);
        float* op = &g_part[(((size_t)ig*BB + b)*NN + (j0 + edj))*DD + n0e];
        const float z = sawz ? 0.0f : -CUDART_INF_F;
        float4 o;
        o.x = fmaxf(rmax[0] + m1.x, z);
        o.y = fmaxf(rmax[1] + m1.y, z);
        o.z = fmaxf(rmax[2] + m1.z, z);
        o.w = fmaxf(rmax[3] + m1.w, z);
        *(float4*)op = o;
    }
}

// -------- output head: reduce partials + Wo2 GEMM, 4 rows per block --------
__global__ void k_final(const float* __restrict__ Wo2, const float* __restrict__ bo2,
                        float* __restrict__ ret) {
    __shared__ float ms[4][DD];
    const int row0 = blockIdx.x * 4;
    const int t = threadIdx.x;      // 128
    #pragma unroll
    for (int r = 0; r < 4; r++) {
        float v = -CUDART_INF_F;
        #pragma unroll
        for (int g = 0; g < IGRP; g++)
            v = fmaxf(v, g_part[(size_t)g*BB*NN*DD + (size_t)(row0 + r)*DD + t]);
        ms[r][t] = v;
    }
    __syncthreads();
    float acc[4];
    const float bia = bo2[t];
    #pragma unroll
    for (int r = 0; r < 4; r++) acc[r] = g_o1[(row0 + r)*DD + t] + bia;
    for (int k = 0; k < DD; k++) {
        float w = Wo2[k*DD + t];
        #pragma unroll
        for (int r = 0; r < 4; r++) acc[r] += ms[r][k] * w;
    }
    #pragma unroll
    for (int r = 0; r < 4; r++) ret[(row0 + r)*DD + t] = acc[r];
}

extern "C" void kernel_launch(void* const* d_in, const int* in_sizes, int n_in,
                              void* d_out, int out_size) {
    (void)in_sizes; (void)n_in; (void)out_size;
    const float* node   = (const float*)d_in[0];
    const float* edge   = (const float*)d_in[1];
    const float* graph  = (const float*)d_in[2];
    const float* adj    = (const float*)d_in[3];
    const float* hidden = (const float*)d_in[4];
    const float* Wm1 = (const float*)d_in[5],  *bm1 = (const float*)d_in[6];
    const float* Wm2 = (const float*)d_in[7],  *bm2 = (const float*)d_in[8];
    const float* Wme = (const float*)d_in[9],  *bme = (const float*)d_in[10];
    const float* Wmg = (const float*)d_in[11], *bmg = (const float*)d_in[12];
    const float* Wo1 = (const float*)d_in[13], *bo1 = (const float*)d_in[14];
    const float* Wo2 = (const float*)d_in[15], *bo2 = (const float*)d_in[16];
    const float* Wt1 = (const float*)d_in[17], *bt1 = (const float*)d_in[18];
    const float* Wt2 = (const float*)d_in[19], *bt2 = (const float*)d_in[20];
    const float* Wte = (const float*)d_in[21], *bte = (const float*)d_in[22];
    const float* Wtg = (const float*)d_in[23], *btg = (const float*)d_in[24];

    float* ret = (float*)d_out;
    float* tri = (float*)d_out + (size_t)BB*NN*DD;

    cudaFuncSetAttribute(k_main, cudaFuncAttributeMaxDynamicSharedMemorySize, SMEM_MAIN);

    k_graph<<<BB, 128>>>(graph, Wmg, bmg, Wtg, btg);
    k_node<<<BB*NN/8, 128>>>(node, hidden, Wm1, bm1, Wm2, bm2, bme,
                             Wo1, bo1, Wt1, bt1, Wt2, bt2, bte);
    for (int ig_base = 0; ig_base < IGRP; ig_base += 2)
        k_main<<<dim3(NN/TJ, 2, BB), NTH, SMEM_MAIN>>>(edge, adj, Wme, Wte, tri, ig_base);
    k_final<<<BB*NN/4, 128>>>(Wo2, bo2, ret);
}